// round 4
// baseline (speedup 1.0000x reference)
#include <cuda_runtime.h>
#include <cuda_bf16.h>

#define NB       4096
#define NINPUTS  41024
#define N4       (NINPUTS / 4)     // 10256 float4 per perspective row
#define TOT4     (2 * N4)          // 20512 combined (w then b)
#define NL1      128
#define NL2      32
#define NL3      32
#define CAPS     192
#define NT       256
#define U        8                 // float4 loads in flight per thread
#define NBLK     740               // 148 SMs * 5 resident blocks

// One persistent fused kernel, 5 blocks/SM. Each block processes ~5.5 rows:
// stream-scan both perspective rows (MLP=8, evict-first), compact to shared,
// gather L2-resident W_ft, run clipped MLP tail. Gather/tail bubbles (~12% of
// a row) are hidden by the 4 other resident blocks' scans.
__global__ void __launch_bounds__(NT, 5) nnue_fused_kernel(
    const float* __restrict__ us,   const float* __restrict__ them,
    const float* __restrict__ w_in, const float* __restrict__ b_in,
    const float* __restrict__ W_ft, const float* __restrict__ b_ft,
    const float* __restrict__ W1,   const float* __restrict__ b1,
    const float* __restrict__ W2,   const float* __restrict__ b2,
    const float* __restrict__ Wo,   const float* __restrict__ bo,
    float* __restrict__ out)
{
    __shared__ int   s_e[CAPS];         // (p<<16) | feature index
    __shared__ float s_v[CAPS];
    __shared__ int   s_cnt;
    __shared__ float s_pw[2][NL1];      // per-group partial accumulators
    __shared__ float s_pb[2][NL1];
    __shared__ float s_l0[2 * NL1];
    __shared__ float s_p1[8][NL2];
    __shared__ float s_l1[NL2];
    __shared__ float s_l2[NL3];

    const int tid = threadIdx.x;

    for (int row = blockIdx.x; row < NB; row += gridDim.x) {
        const float4* __restrict__ w4 = (const float4*)(w_in + (size_t)row * NINPUTS);
        const float4* __restrict__ b4 = (const float4*)(b_in + (size_t)row * NINPUTS);

        if (tid == 0) s_cnt = 0;
        __syncthreads();

        // ---- Fused scan of both perspectives, 8 loads in flight ----
        #pragma unroll 1
        for (int base = 0; base < TOT4; base += NT * U) {
            float4 v[U];
            #pragma unroll
            for (int u = 0; u < U; ++u) {
                const int i = base + u * NT + tid;
                if (i < TOT4) {
                    const float4* p4 = (i < N4) ? (w4 + i) : (b4 + (i - N4));
                    v[u] = __ldcs(p4);           // evict-first: keep W_ft in L2
                } else {
                    v[u] = make_float4(0.f, 0.f, 0.f, 0.f);
                }
            }
            #pragma unroll
            for (int u = 0; u < U; ++u) {
                const float4 vv = v[u];
                if (vv.x != 0.f || vv.y != 0.f || vv.z != 0.f || vv.w != 0.f) {
                    const int i   = base + u * NT + tid;
                    const int p   = (i >= N4);
                    const int col = (i - p * N4) * 4;
                    const int tag = p << 16;
                    if (vv.x != 0.f) { int q = atomicAdd(&s_cnt, 1); if (q < CAPS) { s_e[q] = tag | (col + 0); s_v[q] = vv.x; } }
                    if (vv.y != 0.f) { int q = atomicAdd(&s_cnt, 1); if (q < CAPS) { s_e[q] = tag | (col + 1); s_v[q] = vv.y; } }
                    if (vv.z != 0.f) { int q = atomicAdd(&s_cnt, 1); if (q < CAPS) { s_e[q] = tag | (col + 2); s_v[q] = vv.z; } }
                    if (vv.w != 0.f) { int q = atomicAdd(&s_cnt, 1); if (q < CAPS) { s_e[q] = tag | (col + 3); s_v[q] = vv.w; } }
                }
            }
        }
        __syncthreads();

        // ---- Gather W_ft rows: 2 groups x 128 threads, strided features ----
        {
            const int cnt = min(s_cnt, CAPS);
            const int j = tid & (NL1 - 1);
            const int g = tid >> 7;         // group 0..1
            float aw = 0.f, ab = 0.f;
            #pragma unroll 2
            for (int f = g; f < cnt; f += 2) {
                const int   e    = s_e[f];
                const int   idx  = e & 0xFFFF;
                const float prod = s_v[f] * W_ft[idx * NL1 + j];  // coalesced, L2-hit
                if (e & (1 << 16)) ab += prod; else aw += prod;
            }
            s_pw[g][j] = aw;
            s_pb[g][j] = ab;
        }
        __syncthreads();

        // ---- l0: reduce partials + bias, perspective select, clip ----
        const float u = us[row];
        const float t = them[row];
        {
            const int p = tid >> 7;          // which half of l0
            const int j = tid & (NL1 - 1);
            const float bias = b_ft[j];
            const float accw = bias + s_pw[0][j] + s_pw[1][j];
            const float accb = bias + s_pb[0][j] + s_pb[1][j];
            const float wv = p ? accb : accw;
            const float bv = p ? accw : accb;
            const float v = u * wv + t * bv;
            s_l0[tid] = fminf(fmaxf(v, 0.f), 1.f);
        }
        __syncthreads();

        // ---- l1 = clip(l0 @ W1 + b1): 8 segments x 32 outputs ----
        {
            const int seg = tid >> 5;
            const int o   = tid & 31;
            float a = 0.f;
            #pragma unroll
            for (int i = 0; i < 32; ++i)
                a += s_l0[seg * 32 + i] * W1[(seg * 32 + i) * NL2 + o];
            s_p1[seg][o] = a;
        }
        __syncthreads();
        if (tid < NL2) {
            float a = b1[tid];
            #pragma unroll
            for (int g = 0; g < 8; ++g) a += s_p1[g][tid];
            s_l1[tid] = fminf(fmaxf(a, 0.f), 1.f);
        }
        __syncthreads();

        // ---- l2 = clip(l1 @ W2 + b2) ----
        if (tid < NL3) {
            float a = b2[tid];
            #pragma unroll
            for (int i = 0; i < NL2; ++i)
                a += s_l1[i] * W2[i * NL3 + tid];
            s_l2[tid] = fminf(fmaxf(a, 0.f), 1.f);
        }
        __syncthreads();

        // ---- out = l2 @ Wo + bo ----
        if (tid < 32) {
            float a = s_l2[tid] * Wo[tid];
            #pragma unroll
            for (int off = 16; off > 0; off >>= 1)
                a += __shfl_down_sync(0xffffffffu, a, off);
            if (tid == 0) out[row] = a + bo[0];
        }
        __syncthreads();   // protect shared reuse before next row
    }
}

extern "C" void kernel_launch(void* const* d_in, const int* in_sizes, int n_in,
                              void* d_out, int out_size) {
    const float* us   = (const float*)d_in[0];
    const float* them = (const float*)d_in[1];
    const float* w_in = (const float*)d_in[2];
    const float* b_in = (const float*)d_in[3];
    const float* W_ft = (const float*)d_in[4];
    const float* b_ft = (const float*)d_in[5];
    const float* W1   = (const float*)d_in[6];
    const float* b1   = (const float*)d_in[7];
    const float* W2   = (const float*)d_in[8];
    const float* b2   = (const float*)d_in[9];
    const float* Wo   = (const float*)d_in[10];
    const float* bo   = (const float*)d_in[11];
    float* out = (float*)d_out;

    nnue_fused_kernel<<<NBLK, NT>>>(us, them, w_in, b_in, W_ft, b_ft,
                                    W1, b1, W2, b2, Wo, bo, out);
}

// round 6
// speedup vs baseline: 1.0508x; 1.0508x over previous
#include <cuda_runtime.h>
#include <cuda_bf16.h>

#define NB       4096
#define NINPUTS  41024
#define N4       (NINPUTS / 4)     // 10256 float4 per perspective row
#define TOT4     (2 * N4)          // 20512 combined (w then b)
#define NL1      128
#define NL2      32
#define CAPS     192
#define NT       256
#define NPROD    224               // 7 producer warps
#define U        8                 // float4 loads in flight per producer thread
#define NBLK     740               // 148 SMs * 5 resident blocks

__device__ __forceinline__ float clip01(float x) {
    return fminf(fmaxf(x, 0.f), 1.f);
}

// Warp-specialized persistent kernel: warps 0-6 stream-scan both perspective
// rows of row k+1 into a double-buffered compaction list while warp 7
// (consumer) gathers L2-resident W_ft rows and runs the clipped MLP for row k.
// NOTE: only w_in/b_in are accessed as float4 (proven aligned); all weight
// tables use scalar loads (harness sub-buffers are not 16B-aligned).
__global__ void __launch_bounds__(NT, 5) nnue_ws_kernel(
    const float* __restrict__ us,   const float* __restrict__ them,
    const float* __restrict__ w_in, const float* __restrict__ b_in,
    const float* __restrict__ W_ft, const float* __restrict__ b_ft,
    const float* __restrict__ W1,   const float* __restrict__ b1,
    const float* __restrict__ W2,   const float* __restrict__ b2,
    const float* __restrict__ Wo,   const float* __restrict__ bo,
    float* __restrict__ out)
{
    __shared__ int   s_e[2][CAPS];      // (p<<16) | feature index
    __shared__ float s_v[2][CAPS];
    __shared__ int   s_cnt[2];
    __shared__ float s_l0[2 * NL1];     // consumer-private

    const int tid = threadIdx.x;

    if (tid < 2) s_cnt[tid] = 0;
    __syncthreads();

    if (tid < NPROD) {
        // ================= PRODUCER: pure streaming scan =================
        int kb = 0;
        for (int row = blockIdx.x; row < NB; row += gridDim.x) {
            const float4* __restrict__ w4 = (const float4*)(w_in + (size_t)row * NINPUTS);
            const float4* __restrict__ b4 = (const float4*)(b_in + (size_t)row * NINPUTS);

            #pragma unroll 1
            for (int base = 0; base < TOT4; base += NPROD * U) {
                float4 v[U];
                #pragma unroll
                for (int u = 0; u < U; ++u) {
                    const int i = base + u * NPROD + tid;
                    if (i < TOT4) {
                        const float4* p4 = (i < N4) ? (w4 + i) : (b4 + (i - N4));
                        v[u] = __ldcs(p4);       // evict-first: keep W_ft in L2
                    } else {
                        v[u] = make_float4(0.f, 0.f, 0.f, 0.f);
                    }
                }
                #pragma unroll
                for (int u = 0; u < U; ++u) {
                    const float4 vv = v[u];
                    if (vv.x != 0.f || vv.y != 0.f || vv.z != 0.f || vv.w != 0.f) {
                        const int i   = base + u * NPROD + tid;
                        const int p   = (i >= N4);
                        const int col = (i - p * N4) * 4;
                        const int tag = p << 16;
                        if (vv.x != 0.f) { int q = atomicAdd(&s_cnt[kb], 1); if (q < CAPS) { s_e[kb][q] = tag | (col + 0); s_v[kb][q] = vv.x; } }
                        if (vv.y != 0.f) { int q = atomicAdd(&s_cnt[kb], 1); if (q < CAPS) { s_e[kb][q] = tag | (col + 1); s_v[kb][q] = vv.y; } }
                        if (vv.z != 0.f) { int q = atomicAdd(&s_cnt[kb], 1); if (q < CAPS) { s_e[kb][q] = tag | (col + 2); s_v[kb][q] = vv.z; } }
                        if (vv.w != 0.f) { int q = atomicAdd(&s_cnt[kb], 1); if (q < CAPS) { s_e[kb][q] = tag | (col + 3); s_v[kb][q] = vv.w; } }
                    }
                }
            }
            __syncthreads();       // handoff row k to consumer
            kb ^= 1;
        }
    } else {
        // ================= CONSUMER: gather + clipped MLP ================
        const int lane = tid & 31;
        int kb = 0;
        for (int row = blockIdx.x; row < NB; row += gridDim.x) {
            __syncthreads();       // wait for producers to finish this row

            int cnt;
            if (lane == 0) { cnt = s_cnt[kb]; s_cnt[kb] = 0; }   // latch + reset
            cnt = min(__shfl_sync(0xffffffffu, cnt, 0), CAPS);

            // Gather: lane owns dims lane, lane+32, lane+64, lane+96.
            // Warp reads one contiguous 512B W_ft row per feature (L2-hit).
            float aw0 = 0.f, aw1 = 0.f, aw2 = 0.f, aw3 = 0.f;
            float ab0 = 0.f, ab1 = 0.f, ab2 = 0.f, ab3 = 0.f;
            #pragma unroll 4
            for (int f = 0; f < cnt; ++f) {
                const int   e   = s_e[kb][f];
                const float val = s_v[kb][f];
                const float* wr = W_ft + (e & 0xFFFF) * NL1 + lane;
                const float w0 = __ldg(wr);
                const float w1 = __ldg(wr + 32);
                const float w2 = __ldg(wr + 64);
                const float w3 = __ldg(wr + 96);
                if (e & (1 << 16)) {
                    ab0 += val * w0; ab1 += val * w1; ab2 += val * w2; ab3 += val * w3;
                } else {
                    aw0 += val * w0; aw1 += val * w1; aw2 += val * w2; aw3 += val * w3;
                }
            }
            aw0 += __ldg(&b_ft[lane]);       ab0 += __ldg(&b_ft[lane]);
            aw1 += __ldg(&b_ft[lane + 32]);  ab1 += __ldg(&b_ft[lane + 32]);
            aw2 += __ldg(&b_ft[lane + 64]);  ab2 += __ldg(&b_ft[lane + 64]);
            aw3 += __ldg(&b_ft[lane + 96]);  ab3 += __ldg(&b_ft[lane + 96]);

            // l0: perspective select + clip. s_l0[0:128]=us-side, [128:256]=them-side
            const float uu = __ldg(&us[row]);
            const float tt = __ldg(&them[row]);
            s_l0[lane]             = clip01(uu * aw0 + tt * ab0);
            s_l0[lane + 32]        = clip01(uu * aw1 + tt * ab1);
            s_l0[lane + 64]        = clip01(uu * aw2 + tt * ab2);
            s_l0[lane + 96]        = clip01(uu * aw3 + tt * ab3);
            s_l0[NL1 + lane]       = clip01(uu * ab0 + tt * aw0);
            s_l0[NL1 + lane + 32]  = clip01(uu * ab1 + tt * aw1);
            s_l0[NL1 + lane + 64]  = clip01(uu * ab2 + tt * aw2);
            s_l0[NL1 + lane + 96]  = clip01(uu * ab3 + tt * aw3);
            __syncwarp();

            // l1 = clip(l0 @ W1 + b1): lane owns output o=lane, 256 terms
            float a1 = __ldg(&b1[lane]);
            #pragma unroll 8
            for (int i = 0; i < 2 * NL1; ++i)
                a1 += s_l0[i] * __ldg(&W1[i * NL2 + lane]);
            const float l1v = clip01(a1);
            __syncwarp();

            // l2 = clip(l1 @ W2 + b2): broadcast l1 via shuffles
            float a2 = __ldg(&b2[lane]);
            #pragma unroll
            for (int i = 0; i < NL2; ++i) {
                const float li = __shfl_sync(0xffffffffu, l1v, i);
                a2 += li * __ldg(&W2[i * NL2 + lane]);
            }
            const float l2v = clip01(a2);

            // out = l2 @ Wo + bo
            float r = l2v * __ldg(&Wo[lane]);
            #pragma unroll
            for (int off = 16; off > 0; off >>= 1)
                r += __shfl_down_sync(0xffffffffu, r, off);
            if (lane == 0) out[row] = r + __ldg(&bo[0]);

            kb ^= 1;
        }
    }
}

extern "C" void kernel_launch(void* const* d_in, const int* in_sizes, int n_in,
                              void* d_out, int out_size) {
    const float* us   = (const float*)d_in[0];
    const float* them = (const float*)d_in[1];
    const float* w_in = (const float*)d_in[2];
    const float* b_in = (const float*)d_in[3];
    const float* W_ft = (const float*)d_in[4];
    const float* b_ft = (const float*)d_in[5];
    const float* W1   = (const float*)d_in[6];
    const float* b1   = (const float*)d_in[7];
    const float* W2   = (const float*)d_in[8];
    const float* b2   = (const float*)d_in[9];
    const float* Wo   = (const float*)d_in[10];
    const float* bo   = (const float*)d_in[11];
    float* out = (float*)d_out;

    nnue_ws_kernel<<<NBLK, NT>>>(us, them, w_in, b_in, W_ft, b_ft,
                                 W1, b1, W2, b2, Wo, bo, out);
}